// round 10
// baseline (speedup 1.0000x reference)
#include <cuda_runtime.h>

#define BATCH 64
#define NPTS  8192
#define SGRID 384
#define OUTD  128
#define CELLS (BATCH * OUTD * OUTD)      // 1,048,576 padded cells (float4)

__device__ float4 d_scratch [CELLS];     // 16MB; ZERO on entry (module init +
                                         // restored by k_compact every call)
__device__ int2   d_blockmin[BATCH * 8];
__device__ uint4  d_gpack   [BATCH * NPTS / 4];

// Single 16B vector reduction — sm_90+; 16B-aligned address.
__device__ __forceinline__ void red_add_v4f32(float* p, float a, float b, float c) {
    asm volatile("red.global.add.v4.f32 [%0], {%1, %2, %3, %4};"
                 :: "l"(p), "f"(a), "f"(b), "f"(c), "f"(0.0f) : "memory");
}

// ---------------------------------------------------------------------------
// k1: lattice math, 4 points/thread, vectorized I/O. 512 blocks x 256 thr.
// ---------------------------------------------------------------------------
__global__ void __launch_bounds__(256) k_compute(const float* __restrict__ pc1,
                                                 const float* __restrict__ tmat)
{
    const int b    = blockIdx.x >> 3;            // 8 blocks per batch
    const int base = (blockIdx.x & 7) << 10;     // 1024 points per block
    const int n0   = base + (threadIdx.x << 2);  // 4 consecutive points

    __shared__ float M[9];
    if (threadIdx.x < 9) M[threadIdx.x] = tmat[b * 9 + threadIdx.x];
    __syncthreads();

    const float* p = pc1 + (size_t)b * 3 * NPTS + n0;
    const float4 P0 = *reinterpret_cast<const float4*>(p);
    const float4 P1 = *reinterpret_cast<const float4*>(p + NPTS);
    const float4 P2 = *reinterpret_cast<const float4*>(p + 2 * NPTS);

    unsigned pk[4];
    int mm0 = 0x7FFFFFFF, mm1 = 0x7FFFFFFF;

    #pragma unroll
    for (int k = 0; k < 4; k++) {
        const float p0 = (&P0.x)[k], p1 = (&P1.x)[k], p2 = (&P2.x)[k];

        const float e0 = M[0] * p0 + M[1] * p1 + M[2] * p2;
        const float e1 = M[3] * p0 + M[4] * p1 + M[5] * p2;
        const float e2 = M[6] * p0 + M[7] * p1 + M[8] * p2;

        // greedy = round(e/3)*3 (IEEE div + round-half-even, matching jnp)
        const float q0 = rintf(__fdiv_rn(e0, 3.0f));
        const float q1 = rintf(__fdiv_rn(e1, 3.0f));
        const float q2 = rintf(__fdiv_rn(e2, 3.0f));
        const float d0 = e0 - 3.0f * q0;
        const float d1 = e1 - 3.0f * q1;
        const float d2 = e2 - 3.0f * q2;

        const int i0 = (int)q0, i1 = (int)q1, i2 = (int)q2;
        const int rs = i0 + i1 + i2;             // remainder_sum (exact)

        // rank = inverse of stable descending argsort of (d0,d1,d2)
        int rk0 = (d1 > d0) + (d2 > d0);
        int rk1 = (d0 > d1) + (d2 > d1) + (d0 == d1);

        int g0 = 3 * i0;
        int g1 = 3 * i1;

        int sh0 = 0, sh1 = 0;
        if (rs > 0) {
            const int thr = 3 - rs;
            sh0 = (rk0 >= thr) ? -3 : 0;
            sh1 = (rk1 >= thr) ? -3 : 0;
        } else if (rs < 0) {
            sh0 = (rk0 < -rs) ? 3 : 0;
            sh1 = (rk1 < -rs) ? 3 : 0;
        }
        g0 += sh0;  g1 += sh1;
        rk0 += sh0 + rs;
        rk1 += sh1 + rs;

        // JAX gather semantics for CANONICAL[rank]: wrap negatives +3, clamp [0,2]
        int cr0 = (rk0 < 0) ? rk0 + 3 : rk0;  cr0 = min(max(cr0, 0), 2);
        int cr1 = (rk1 < 0) ? rk1 + 3 : rk1;  cr1 = min(max(cr1, 0), 2);

        mm0 = min(mm0, g0 - cr0);   // min_r CANONICAL[cr][r] == -cr
        mm1 = min(mm1, g1 - cr1);

        pk[k] = (unsigned)(g0 + 1024) | ((unsigned)(g1 + 1024) << 16);
    }

    d_gpack[(b * NPTS + n0) >> 2] = make_uint4(pk[0], pk[1], pk[2], pk[3]);

    // block min-reduction -> one int2 store
    #pragma unroll
    for (int o = 16; o; o >>= 1) {
        mm0 = min(mm0, __shfl_xor_sync(0xFFFFFFFFu, mm0, o));
        mm1 = min(mm1, __shfl_xor_sync(0xFFFFFFFFu, mm1, o));
    }
    __shared__ int s0[8], s1[8];
    if ((threadIdx.x & 31) == 0) {
        s0[threadIdx.x >> 5] = mm0;
        s1[threadIdx.x >> 5] = mm1;
    }
    __syncthreads();
    if (threadIdx.x == 0) {
        int a = s0[0], c = s1[0];
        #pragma unroll
        for (int w = 1; w < 8; w++) { a = min(a, s0[w]); c = min(c, s1[w]); }
        d_blockmin[blockIdx.x] = make_int2(a, c);
    }
}

// ---------------------------------------------------------------------------
// k2: per-batch offset + one red.v4 per point. 512 blocks x 256 thr, 4 pts.
// ---------------------------------------------------------------------------
__global__ void __launch_bounds__(256) k_scatter(const float* __restrict__ feat)
{
    const int b    = blockIdx.x >> 3;
    const int base = (blockIdx.x & 7) << 10;
    const int n0   = base + (threadIdx.x << 2);

    __shared__ int soff0, soff1;
    if (threadIdx.x < 8) {
        int2 v = d_blockmin[(b << 3) + threadIdx.x];
        int a = v.x, c = v.y;
        #pragma unroll
        for (int o = 4; o; o >>= 1) {
            a = min(a, __shfl_xor_sync(0xFFu, a, o));
            c = min(c, __shfl_xor_sync(0xFFu, c, o));
        }
        if (threadIdx.x == 0) { soff0 = a; soff1 = c; }
    }

    const uint4 PK = d_gpack[(b * NPTS + n0) >> 2];
    const float* f = feat + (size_t)b * 3 * NPTS + n0;
    const float4 F0 = *reinterpret_cast<const float4*>(f);
    const float4 F1 = *reinterpret_cast<const float4*>(f + NPTS);
    const float4 F2 = *reinterpret_cast<const float4*>(f + 2 * NPTS);

    __syncthreads();
    const int off0 = soff0, off1 = soff1;

    #pragma unroll
    for (int k = 0; k < 4; k++) {
        const unsigned pk = (&PK.x)[k];
        const int row = ((int)(pk & 0xFFFFu) - 1024) - off0;   // >= 0
        const int col = ((int)(pk >> 16)     - 1024) - off1;
        if (row < SGRID && col < SGRID) {
            const int u = row / 3;       // row ≡ pts_pick0 (mod 3) exactly
            const int v = col / 3;
            const int idx = (b << 14) + (u << 7) + v;
            red_add_v4f32(&d_scratch[idx].x, (&F0.x)[k], (&F1.x)[k], (&F2.x)[k]);
        }
    }
}

// ---------------------------------------------------------------------------
// k3: compact scratch -> out AND restore scratch to zero.
// Block owns cells [1024*blk, 1024*blk+1024) and out-f4 [768*blk, +768):
// all reads stay inside the block's window, so zeroing after __syncthreads
// is race-free. 1024 blocks x 256 threads.
// ---------------------------------------------------------------------------
__global__ void __launch_bounds__(256) k_compact(float* __restrict__ out)
{
    const int cellBase = blockIdx.x << 10;
    float4* o4 = reinterpret_cast<float4*>(out) + ((size_t)blockIdx.x * 768);

    #pragma unroll
    for (int k = 0; k < 3; k++) {
        const int q  = (k << 8) + threadIdx.x;   // local out-f4 index [0,768)
        const int fl = q << 2;
        const int c0 = fl / 3;                   // local cell [0,1023)
        const int r  = q % 3;

        const float4 A = d_scratch[cellBase + c0];
        const float4 B = d_scratch[cellBase + c0 + 1];

        float4 v;                                 // window (A.xyz B.xyz)[r, r+4)
        v.x = (r == 0) ? A.x : ((r == 1) ? A.y : A.z);
        v.y = (r == 0) ? A.y : ((r == 1) ? A.z : B.x);
        v.z = (r == 0) ? A.z : ((r == 1) ? B.x : B.y);
        v.w = (r == 0) ? B.x : ((r == 1) ? B.y : B.z);
        o4[q] = v;
    }

    __syncthreads();   // all reads of this block's window done

    const float4 z = make_float4(0.f, 0.f, 0.f, 0.f);
    #pragma unroll
    for (int k = 0; k < 4; k++)
        d_scratch[cellBase + (k << 8) + threadIdx.x] = z;
}

// ---------------------------------------------------------------------------
extern "C" void kernel_launch(void* const* d_in, const int* in_sizes, int n_in,
                              void* d_out, int out_size)
{
    const float* pc1  = (const float*)d_in[0];
    const float* feat = (const float*)d_in[1];
    const float* tmat = (const float*)d_in[2];
    float*       out  = (float*)d_out;

    k_compute<<<512, 256>>>(pc1, tmat);
    k_scatter<<<512, 256>>>(feat);
    k_compact<<<1024, 256>>>(out);
}

// round 11
// speedup vs baseline: 1.1025x; 1.1025x over previous
#include <cuda_runtime.h>

#define BATCH 64
#define NPTS  8192
#define SGRID 384
#define OUTD  128
#define CELLS (BATCH * OUTD * OUTD)      // 1,048,576 padded cells (float4)

__device__ float4 d_scratch [CELLS];     // 16MB; ZERO on entry (module-load BSS
                                         // init + restored by k_compact each call)
__device__ int2   d_blockmin[BATCH * 16];
__device__ uint2  d_gpack   [BATCH * NPTS / 2];

// Single 16B vector reduction — sm_90+; 16B-aligned address.
__device__ __forceinline__ void red_add_v4f32(float* p, float a, float b, float c) {
    asm volatile("red.global.add.v4.f32 [%0], {%1, %2, %3, %4};"
                 :: "l"(p), "f"(a), "f"(b), "f"(c), "f"(0.0f) : "memory");
}

// ---------------------------------------------------------------------------
// k1: lattice math only (no zero-fill). 1024 blocks x 256 thr, 2 pts/thread.
// 6.9 blocks/SM resident -> ~86% occupancy; regs capped by launch_bounds.
// ---------------------------------------------------------------------------
__global__ void __launch_bounds__(256, 7)
k_compute(const float* __restrict__ pc1, const float* __restrict__ tmat)
{
    const int b    = blockIdx.x >> 4;            // 16 blocks per batch
    const int base = (blockIdx.x & 15) << 9;     // 512 points per block
    const int n0   = base + (threadIdx.x << 1);  // 2 consecutive points

    __shared__ float M[9];
    if (threadIdx.x < 9) M[threadIdx.x] = tmat[b * 9 + threadIdx.x];
    __syncthreads();

    const float* p = pc1 + (size_t)b * 3 * NPTS + n0;
    const float2 P0 = *reinterpret_cast<const float2*>(p);
    const float2 P1 = *reinterpret_cast<const float2*>(p + NPTS);
    const float2 P2 = *reinterpret_cast<const float2*>(p + 2 * NPTS);

    unsigned pk[2];
    int mm0 = 0x7FFFFFFF, mm1 = 0x7FFFFFFF;

    #pragma unroll
    for (int k = 0; k < 2; k++) {
        const float p0 = (&P0.x)[k], p1 = (&P1.x)[k], p2 = (&P2.x)[k];

        const float e0 = M[0] * p0 + M[1] * p1 + M[2] * p2;
        const float e1 = M[3] * p0 + M[4] * p1 + M[5] * p2;
        const float e2 = M[6] * p0 + M[7] * p1 + M[8] * p2;

        // greedy = round(e/3)*3 (IEEE div + round-half-even, matching jnp)
        const float q0 = rintf(__fdiv_rn(e0, 3.0f));
        const float q1 = rintf(__fdiv_rn(e1, 3.0f));
        const float q2 = rintf(__fdiv_rn(e2, 3.0f));
        const float d0 = e0 - 3.0f * q0;
        const float d1 = e1 - 3.0f * q1;
        const float d2 = e2 - 3.0f * q2;

        const int i0 = (int)q0, i1 = (int)q1, i2 = (int)q2;
        const int rs = i0 + i1 + i2;             // remainder_sum (exact)

        // rank = inverse of stable descending argsort of (d0,d1,d2)
        int rk0 = (d1 > d0) + (d2 > d0);
        int rk1 = (d0 > d1) + (d2 > d1) + (d0 == d1);

        int g0 = 3 * i0;
        int g1 = 3 * i1;

        int sh0 = 0, sh1 = 0;
        if (rs > 0) {
            const int thr = 3 - rs;
            sh0 = (rk0 >= thr) ? -3 : 0;
            sh1 = (rk1 >= thr) ? -3 : 0;
        } else if (rs < 0) {
            sh0 = (rk0 < -rs) ? 3 : 0;
            sh1 = (rk1 < -rs) ? 3 : 0;
        }
        g0 += sh0;  g1 += sh1;
        rk0 += sh0 + rs;
        rk1 += sh1 + rs;

        // JAX gather semantics for CANONICAL[rank]: wrap negatives +3, clamp [0,2]
        int cr0 = (rk0 < 0) ? rk0 + 3 : rk0;  cr0 = min(max(cr0, 0), 2);
        int cr1 = (rk1 < 0) ? rk1 + 3 : rk1;  cr1 = min(max(cr1, 0), 2);

        mm0 = min(mm0, g0 - cr0);   // min_r CANONICAL[cr][r] == -cr
        mm1 = min(mm1, g1 - cr1);

        pk[k] = (unsigned)(g0 + 1024) | ((unsigned)(g1 + 1024) << 16);
    }

    d_gpack[(b * NPTS + n0) >> 1] = make_uint2(pk[0], pk[1]);

    // block min-reduction -> one int2 store
    #pragma unroll
    for (int o = 16; o; o >>= 1) {
        mm0 = min(mm0, __shfl_xor_sync(0xFFFFFFFFu, mm0, o));
        mm1 = min(mm1, __shfl_xor_sync(0xFFFFFFFFu, mm1, o));
    }
    __shared__ int s0[8], s1[8];
    if ((threadIdx.x & 31) == 0) {
        s0[threadIdx.x >> 5] = mm0;
        s1[threadIdx.x >> 5] = mm1;
    }
    __syncthreads();
    if (threadIdx.x == 0) {
        int a = s0[0], c = s1[0];
        #pragma unroll
        for (int w = 1; w < 8; w++) { a = min(a, s0[w]); c = min(c, s1[w]); }
        d_blockmin[blockIdx.x] = make_int2(a, c);
    }
}

// ---------------------------------------------------------------------------
// k2: per-batch offset + one red.v4 per point. 1024 blocks x 256 thr, 2 pts.
// ---------------------------------------------------------------------------
__global__ void __launch_bounds__(256, 7)
k_scatter(const float* __restrict__ feat)
{
    const int b    = blockIdx.x >> 4;
    const int base = (blockIdx.x & 15) << 9;
    const int n0   = base + (threadIdx.x << 1);

    __shared__ int soff0, soff1;
    if (threadIdx.x < 16) {
        int2 v = d_blockmin[(b << 4) + threadIdx.x];
        int a = v.x, c = v.y;
        #pragma unroll
        for (int o = 8; o; o >>= 1) {
            a = min(a, __shfl_xor_sync(0xFFFFu, a, o));
            c = min(c, __shfl_xor_sync(0xFFFFu, c, o));
        }
        if (threadIdx.x == 0) { soff0 = a; soff1 = c; }
    }

    const uint2 PK = d_gpack[(b * NPTS + n0) >> 1];
    const float* f = feat + (size_t)b * 3 * NPTS + n0;
    const float2 F0 = *reinterpret_cast<const float2*>(f);
    const float2 F1 = *reinterpret_cast<const float2*>(f + NPTS);
    const float2 F2 = *reinterpret_cast<const float2*>(f + 2 * NPTS);

    __syncthreads();
    const int off0 = soff0, off1 = soff1;

    #pragma unroll
    for (int k = 0; k < 2; k++) {
        const unsigned pk = (&PK.x)[k];
        const int row = ((int)(pk & 0xFFFFu) - 1024) - off0;   // >= 0
        const int col = ((int)(pk >> 16)     - 1024) - off1;
        if (row < SGRID && col < SGRID) {
            const int u = row / 3;       // row ≡ pts_pick0 (mod 3) exactly
            const int v = col / 3;
            const int idx = (b << 14) + (u << 7) + v;
            red_add_v4f32(&d_scratch[idx].x, (&F0.x)[k], (&F1.x)[k], (&F2.x)[k]);
        }
    }
}

// ---------------------------------------------------------------------------
// k3: compact scratch (16B cells) -> out (12B cells) AND restore scratch to
// zero. Block owns cells [1024*blk, +1024) and out-f4 [768*blk, +768); reads
// stay in-window so post-sync zeroing is race-free. All 6 loads issued before
// assembly for MLP. 1024 blocks x 256 threads.
// ---------------------------------------------------------------------------
__global__ void __launch_bounds__(256) k_compact(float* __restrict__ out)
{
    const int cellBase = blockIdx.x << 10;
    float4* o4 = reinterpret_cast<float4*>(out) + ((size_t)blockIdx.x * 768);

    int   q[3], r[3];
    float4 A[3], B[3];
    #pragma unroll
    for (int k = 0; k < 3; k++) {
        q[k] = (k << 8) + threadIdx.x;           // local out-f4 index [0,768)
        const int c0 = (q[k] << 2) / 3;          // local cell [0,1023)
        r[k] = q[k] % 3;
        A[k] = __ldg(&d_scratch[cellBase + c0]);
        B[k] = __ldg(&d_scratch[cellBase + c0 + 1]);
    }
    #pragma unroll
    for (int k = 0; k < 3; k++) {
        float4 v;                                 // window (A.xyz B.xyz)[r, r+4)
        v.x = (r[k] == 0) ? A[k].x : ((r[k] == 1) ? A[k].y : A[k].z);
        v.y = (r[k] == 0) ? A[k].y : ((r[k] == 1) ? A[k].z : B[k].x);
        v.z = (r[k] == 0) ? A[k].z : ((r[k] == 1) ? B[k].x : B[k].y);
        v.w = (r[k] == 0) ? B[k].x : ((r[k] == 1) ? B[k].y : B[k].z);
        o4[q[k]] = v;
    }

    __syncthreads();   // all reads of this block's window done

    const float4 z = make_float4(0.f, 0.f, 0.f, 0.f);
    #pragma unroll
    for (int k = 0; k < 4; k++)
        d_scratch[cellBase + (k << 8) + threadIdx.x] = z;
}

// ---------------------------------------------------------------------------
extern "C" void kernel_launch(void* const* d_in, const int* in_sizes, int n_in,
                              void* d_out, int out_size)
{
    const float* pc1  = (const float*)d_in[0];
    const float* feat = (const float*)d_in[1];
    const float* tmat = (const float*)d_in[2];
    float*       out  = (float*)d_out;

    k_compute<<<1024, 256>>>(pc1, tmat);
    k_scatter<<<1024, 256>>>(feat);
    k_compact<<<1024, 256>>>(out);
}